// round 9
// baseline (speedup 1.0000x reference)
#include <cuda_runtime.h>
#include <math.h>

#define BB   4
#define SSS  12
#define NP   512
#define DD   128
#define HH   8
#define HDp  16
#define MTOT (BB*SSS*NP)   /* 24576 */

// ---------------- scratch (static device arrays; no allocs allowed) ----------
__device__ float g_q [MTOT*DD];
__device__ float g_k [MTOT*DD];
__device__ float g_v [MTOT*DD];
__device__ float g_ao[MTOT*DD];
__device__ unsigned char g_mask[BB*NP*NP];

__constant__ float c_ql[19] = {0.01f,0.1f,0.11f,0.2f,0.21f,0.3f,0.31f,0.4f,0.41f,
                               0.5f,0.51f,0.6f,0.61f,0.7f,0.71f,0.8f,0.81f,0.9f,0.91f};

#define CONGEST_F32 ((float)-0.2260138304488262)

// XLA GPU row-reduction order (16-lane shuffle tree, zero-padded). FROZEN.
__device__ __forceinline__ float xla_tree12(const float* e) {
    float m0 = __fadd_rn(__fadd_rn(e[0], e[8]),  e[4]);
    float m1 = __fadd_rn(__fadd_rn(e[1], e[9]),  e[5]);
    float m2 = __fadd_rn(__fadd_rn(e[2], e[10]), e[6]);
    float m3 = __fadd_rn(__fadd_rn(e[3], e[11]), e[7]);
    return __fadd_rn(__fadd_rn(m0, m2), __fadd_rn(m1, m3));
}

// ---------------------------------------------------------------------------
// Mask kernel — numerics FROZEN (bit-exact vs reference as of R8).
// ---------------------------------------------------------------------------
__global__ __launch_bounds__(512) void mask_kernel(const float* __restrict__ x,
                                                   unsigned char* __restrict__ mask) {
    __shared__ float xn[12];
    __shared__ float ss[512];
    __shared__ float sq[19];
    const int n = blockIdx.x, b = blockIdx.y;
    const int t = threadIdx.x;

    if (t < 12) xn[t] = x[(b*NP + n)*12 + t];
    __syncthreads();

    float ad[12], xv[12];
    #pragma unroll
    for (int s2 = 0; s2 < 12; s2++) {
        float xm = x[(b*NP + t)*12 + s2];
        xv[s2] = xm;
        ad[s2] = fabsf(__fadd_rn(xn[s2], -xm));
    }
    const float dist  = xla_tree12(ad);
    const float xmean = __fdiv_rn(xla_tree12(xv), 12.0f);
    ss[t] = dist;
    __syncthreads();

    for (int k = 2; k <= 512; k <<= 1) {
        for (int j = k >> 1; j > 0; j >>= 1) {
            int ixj = t ^ j;
            if (ixj > t) {
                float a = ss[t], c = ss[ixj];
                bool up = ((t & k) == 0);
                if ((a > c) == up) { ss[t] = c; ss[ixj] = a; }
            }
            __syncthreads();
        }
    }

    if (t < 19) {
        float hpos = __fmul_rn(c_ql[t], 511.0f);
        float lo   = floorf(hpos);
        float hw   = __fadd_rn(hpos, -lo);
        float lw   = __fadd_rn(1.0f, -hw);
        int   il   = (int)lo;
        sq[t] = __fmaf_rn(ss[il], lw, __fmul_rn(ss[il+1], hw));
    }
    __syncthreads();

    bool msk = (dist <= sq[0]);
    #pragma unroll
    for (int bnd = 0; bnd < 9; bnd++)
        msk = msk || (dist >= sq[1 + 2*bnd] && dist <= sq[2 + 2*bnd]);
    msk = msk || (xmean <= CONGEST_F32);

    mask[((size_t)b*NP + n)*NP + t] = msk ? (unsigned char)1 : (unsigned char)0;
}

// ---------------------------------------------------------------------------
// Triple-fused SGEMM: C = A @ W^T + bias. 128x128x16 tiles, 8x8 per thread.
// blockIdx.y selects which (A,W,b,C) tuple. fp32 exact (numerics unchanged).
// ---------------------------------------------------------------------------
__global__ __launch_bounds__(256) void gemm3_kernel(
    const float* __restrict__ A0, const float* __restrict__ A1, const float* __restrict__ A2,
    const float* __restrict__ W0, const float* __restrict__ W1, const float* __restrict__ W2,
    const float* __restrict__ b0, const float* __restrict__ b1, const float* __restrict__ b2,
    float* __restrict__ C0, float* __restrict__ C1, float* __restrict__ C2)
{
    const int sel = blockIdx.y;
    const float* A    = sel == 0 ? A0 : (sel == 1 ? A1 : A2);
    const float* W    = sel == 0 ? W0 : (sel == 1 ? W1 : W2);
    const float* bias = sel == 0 ? b0 : (sel == 1 ? b1 : b2);
    float*       C    = sel == 0 ? C0 : (sel == 1 ? C1 : C2);

    __shared__ float As[128][20];
    __shared__ float Ws[128][20];

    const int bm  = blockIdx.x * 128;
    const int tid = threadIdx.x;
    const int tx  = tid & 15, ty = tid >> 4;
    const int lrow = tid >> 2;           // 0..63
    const int lk   = (tid & 3) * 4;      // 0,4,8,12

    float acc[8][8];
    #pragma unroll
    for (int i = 0; i < 8; i++)
        #pragma unroll
        for (int j = 0; j < 8; j++) acc[i][j] = 0.f;

    for (int k0 = 0; k0 < 128; k0 += 16) {
        float4 a0 = *(const float4*)&A[(size_t)(bm+lrow   )*128 + k0 + lk];
        float4 a1 = *(const float4*)&A[(size_t)(bm+lrow+64)*128 + k0 + lk];
        float4 w0 = *(const float4*)&W[(size_t)(lrow   )*128 + k0 + lk];
        float4 w1 = *(const float4*)&W[(size_t)(lrow+64)*128 + k0 + lk];
        *(float4*)&As[lrow   ][lk] = a0;
        *(float4*)&As[lrow+64][lk] = a1;
        *(float4*)&Ws[lrow   ][lk] = w0;
        *(float4*)&Ws[lrow+64][lk] = w1;
        __syncthreads();

        #pragma unroll
        for (int kk = 0; kk < 16; kk++) {
            float a[8], w[8];
            #pragma unroll
            for (int i = 0; i < 4; i++) {
                a[i]   = As[ty*4+i][kk];
                a[4+i] = As[64+ty*4+i][kk];
            }
            #pragma unroll
            for (int j = 0; j < 4; j++) {
                w[j]   = Ws[tx*4+j][kk];
                w[4+j] = Ws[64+tx*4+j][kk];
            }
            #pragma unroll
            for (int i = 0; i < 8; i++)
                #pragma unroll
                for (int j = 0; j < 8; j++)
                    acc[i][j] += a[i] * w[j];
        }
        __syncthreads();
    }

    float4 bA = *(const float4*)&bias[tx*4];
    float4 bB = *(const float4*)&bias[64 + tx*4];
    #pragma unroll
    for (int rg = 0; rg < 2; rg++)
        #pragma unroll
        for (int ii = 0; ii < 4; ii++) {
            const int ai = rg*4 + ii;
            const size_t r = (size_t)(bm + rg*64 + ty*4 + ii);
            float4 o0, o1;
            o0.x = acc[ai][0] + bA.x;  o0.y = acc[ai][1] + bA.y;
            o0.z = acc[ai][2] + bA.z;  o0.w = acc[ai][3] + bA.w;
            o1.x = acc[ai][4] + bB.x;  o1.y = acc[ai][5] + bB.y;
            o1.z = acc[ai][6] + bB.z;  o1.w = acc[ai][7] + bB.w;
            *(float4*)&C[r*128 + tx*4]      = o0;
            *(float4*)&C[r*128 + 64 + tx*4] = o1;
        }
}

// ---------------------------------------------------------------------------
// Attention: one block per (b,s,h); 4-query register blocking, __expf.
// ---------------------------------------------------------------------------
__global__ __launch_bounds__(256) void attn_kernel(const float* __restrict__ gq,
                                                   const float* __restrict__ gk,
                                                   const float* __restrict__ gv,
                                                   const unsigned char* __restrict__ gmask,
                                                   float* __restrict__ gout) {
    extern __shared__ float sh[];          // Kt[16][512] | Vt[16][512]
    float* Kt = sh;
    float* Vt = sh + HDp*NP;

    const int blk = blockIdx.x;
    const int h   = blk & (HH-1);
    const int bs  = blk >> 3;              // b*S + s
    const int b   = bs / SSS;

    const float* kbase = gk + (size_t)bs*NP*DD + h*HDp;
    const float* vbase = gv + (size_t)bs*NP*DD + h*HDp;
    const float* qbase = gq + (size_t)bs*NP*DD + h*HDp;
    float*       obase = gout + (size_t)bs*NP*DD + h*HDp;
    const unsigned char* maskb = gmask + (size_t)b*NP*NP;

    const int tid = threadIdx.x;
    for (int i = tid; i < NP*4; i += 256) {
        int m = i >> 2, d4 = (i & 3) * 4;
        float4 kv = *(const float4*)&kbase[(size_t)m*DD + d4];
        float4 vv = *(const float4*)&vbase[(size_t)m*DD + d4];
        Kt[(d4+0)*NP+m] = kv.x; Kt[(d4+1)*NP+m] = kv.y;
        Kt[(d4+2)*NP+m] = kv.z; Kt[(d4+3)*NP+m] = kv.w;
        Vt[(d4+0)*NP+m] = vv.x; Vt[(d4+1)*NP+m] = vv.y;
        Vt[(d4+2)*NP+m] = vv.z; Vt[(d4+3)*NP+m] = vv.w;
    }
    __syncthreads();

    const int warp = tid >> 5, lane = tid & 31;

    for (int it = 0; it < 16; ++it) {
        const int n0 = warp*64 + it*4;     // queries n0 .. n0+3

        float q[4][16];
        #pragma unroll
        for (int c = 0; c < 4; c++)
            #pragma unroll
            for (int d4 = 0; d4 < 16; d4 += 4) {
                float4 t = *(const float4*)&qbase[(size_t)(n0+c)*DD + d4];
                q[c][d4] = t.x; q[c][d4+1] = t.y; q[c][d4+2] = t.z; q[c][d4+3] = t.w;
            }

        const unsigned char* mr = maskb + (size_t)n0*NP;

        float lg[4][16];
        #pragma unroll
        for (int i = 0; i < 16; i++) {
            const int m = i*32 + lane;
            float s0 = 0.f, s1 = 0.f, s2 = 0.f, s3 = 0.f;
            #pragma unroll
            for (int d = 0; d < 16; d++) {
                float kv = Kt[d*NP + m];
                s0 += q[0][d]*kv; s1 += q[1][d]*kv;
                s2 += q[2][d]*kv; s3 += q[3][d]*kv;
            }
            lg[0][i] = mr[m]        ? s0*0.25f : -INFINITY;
            lg[1][i] = mr[NP+m]     ? s1*0.25f : -INFINITY;
            lg[2][i] = mr[2*NP+m]   ? s2*0.25f : -INFINITY;
            lg[3][i] = mr[3*NP+m]   ? s3*0.25f : -INFINITY;
        }

        float mx[4] = {-INFINITY, -INFINITY, -INFINITY, -INFINITY};
        #pragma unroll
        for (int c = 0; c < 4; c++)
            #pragma unroll
            for (int i = 0; i < 16; i++) mx[c] = fmaxf(mx[c], lg[c][i]);
        #pragma unroll
        for (int off = 16; off; off >>= 1)
            #pragma unroll
            for (int c = 0; c < 4; c++)
                mx[c] = fmaxf(mx[c], __shfl_xor_sync(0xffffffffu, mx[c], off));

        float sm[4] = {0.f, 0.f, 0.f, 0.f};
        #pragma unroll
        for (int c = 0; c < 4; c++)
            #pragma unroll
            for (int i = 0; i < 16; i++) {
                lg[c][i] = __expf(lg[c][i] - mx[c]);
                sm[c] += lg[c][i];
            }
        #pragma unroll
        for (int off = 16; off; off >>= 1)
            #pragma unroll
            for (int c = 0; c < 4; c++)
                sm[c] += __shfl_xor_sync(0xffffffffu, sm[c], off);

        float acc[4][16];
        #pragma unroll
        for (int c = 0; c < 4; c++)
            #pragma unroll
            for (int d = 0; d < 16; d++) acc[c][d] = 0.f;

        #pragma unroll
        for (int i = 0; i < 16; i++) {
            const int m = i*32 + lane;
            const float p0 = lg[0][i], p1 = lg[1][i], p2 = lg[2][i], p3 = lg[3][i];
            #pragma unroll
            for (int d = 0; d < 16; d++) {
                float vv = Vt[d*NP + m];
                acc[0][d] += p0*vv; acc[1][d] += p1*vv;
                acc[2][d] += p2*vv; acc[3][d] += p3*vv;
            }
        }
        #pragma unroll
        for (int off = 16; off; off >>= 1)
            #pragma unroll
            for (int c = 0; c < 4; c++)
                #pragma unroll
                for (int d = 0; d < 16; d++)
                    acc[c][d] += __shfl_xor_sync(0xffffffffu, acc[c][d], off);

        #pragma unroll
        for (int c = 0; c < 4; c++) {
            const float inv = 1.0f / sm[c];
            float w = 0.f;
            #pragma unroll
            for (int d = 0; d < 16; d++)
                if (lane == d) w = acc[c][d];
            if (lane < 16)
                obase[(size_t)(n0+c)*DD + lane] = w * inv;
        }
    }
}

// ---------------------------------------------------------------------------
extern "C" void kernel_launch(void* const* d_in, const int* in_sizes, int n_in,
                              void* d_out, int out_size) {
    const float* query = (const float*)d_in[0];
    const float* key   = (const float*)d_in[1];
    const float* value = (const float*)d_in[2];
    const float* x     = (const float*)d_in[3];
    const float* Wq    = (const float*)d_in[4];
    const float* bq    = (const float*)d_in[5];
    const float* Wk    = (const float*)d_in[6];
    const float* bk    = (const float*)d_in[7];
    const float* Wv    = (const float*)d_in[8];
    const float* bv    = (const float*)d_in[9];
    const float* Wo    = (const float*)d_in[10];
    const float* bo    = (const float*)d_in[11];
    float* out = (float*)d_out;

    float *pq, *pk, *pv, *pao; unsigned char* pmask;
    cudaGetSymbolAddress((void**)&pq,    g_q);
    cudaGetSymbolAddress((void**)&pk,    g_k);
    cudaGetSymbolAddress((void**)&pv,    g_v);
    cudaGetSymbolAddress((void**)&pao,   g_ao);
    cudaGetSymbolAddress((void**)&pmask, g_mask);

    cudaFuncSetAttribute(attn_kernel, cudaFuncAttributeMaxDynamicSharedMemorySize, 65536);

    // 1) LSH mask (frozen numerics)
    mask_kernel<<<dim3(NP, BB), 512>>>(x, pmask);

    // 2) q/k/v projections, fused into one launch
    gemm3_kernel<<<dim3(MTOT/128, 3), 256>>>(query, key, value,
                                             Wq, Wk, Wv,
                                             bq, bk, bv,
                                             pq, pk, pv);

    // 3) attention
    attn_kernel<<<BB*SSS*HH, 256, 65536>>>(pq, pk, pv, pmask, pao);

    // 4) output projection (same kernel, single tuple)
    gemm3_kernel<<<dim3(MTOT/128, 1), 256>>>(pao, pao, pao,
                                             Wo, Wo, Wo,
                                             bo, bo, bo,
                                             out, out, out);
}

// round 10
// speedup vs baseline: 1.7244x; 1.7244x over previous
#include <cuda_runtime.h>
#include <math.h>

#define BB   4
#define SSS  12
#define NP   512
#define DD   128
#define HH   8
#define HDp  16
#define MTOT (BB*SSS*NP)   /* 24576 */

// ---------------- scratch (static device arrays; no allocs allowed) ----------
__device__ float g_q [MTOT*DD];
__device__ float g_k [MTOT*DD];
__device__ float g_v [MTOT*DD];
__device__ float g_ao[MTOT*DD];
__device__ unsigned char g_mask[BB*NP*NP];

__constant__ float c_ql[19] = {0.01f,0.1f,0.11f,0.2f,0.21f,0.3f,0.31f,0.4f,0.41f,
                               0.5f,0.51f,0.6f,0.61f,0.7f,0.71f,0.8f,0.81f,0.9f,0.91f};

#define CONGEST_F32 ((float)-0.2260138304488262)

// XLA GPU row-reduction order (16-lane shuffle tree, zero-padded). FROZEN.
__device__ __forceinline__ float xla_tree12(const float* e) {
    float m0 = __fadd_rn(__fadd_rn(e[0], e[8]),  e[4]);
    float m1 = __fadd_rn(__fadd_rn(e[1], e[9]),  e[5]);
    float m2 = __fadd_rn(__fadd_rn(e[2], e[10]), e[6]);
    float m3 = __fadd_rn(__fadd_rn(e[3], e[11]), e[7]);
    return __fadd_rn(__fadd_rn(m0, m2), __fadd_rn(m1, m3));
}

// ---------------------------------------------------------------------------
// Mask kernel — numerics FROZEN (bit-exact vs reference as of R8).
// ---------------------------------------------------------------------------
__global__ __launch_bounds__(512) void mask_kernel(const float* __restrict__ x,
                                                   unsigned char* __restrict__ mask) {
    __shared__ float xn[12];
    __shared__ float ss[512];
    __shared__ float sq[19];
    const int n = blockIdx.x, b = blockIdx.y;
    const int t = threadIdx.x;

    if (t < 12) xn[t] = x[(b*NP + n)*12 + t];
    __syncthreads();

    float ad[12], xv[12];
    #pragma unroll
    for (int s2 = 0; s2 < 12; s2++) {
        float xm = x[(b*NP + t)*12 + s2];
        xv[s2] = xm;
        ad[s2] = fabsf(__fadd_rn(xn[s2], -xm));
    }
    const float dist  = xla_tree12(ad);
    const float xmean = __fdiv_rn(xla_tree12(xv), 12.0f);
    ss[t] = dist;
    __syncthreads();

    for (int k = 2; k <= 512; k <<= 1) {
        for (int j = k >> 1; j > 0; j >>= 1) {
            int ixj = t ^ j;
            if (ixj > t) {
                float a = ss[t], c = ss[ixj];
                bool up = ((t & k) == 0);
                if ((a > c) == up) { ss[t] = c; ss[ixj] = a; }
            }
            __syncthreads();
        }
    }

    if (t < 19) {
        float hpos = __fmul_rn(c_ql[t], 511.0f);
        float lo   = floorf(hpos);
        float hw   = __fadd_rn(hpos, -lo);
        float lw   = __fadd_rn(1.0f, -hw);
        int   il   = (int)lo;
        sq[t] = __fmaf_rn(ss[il], lw, __fmul_rn(ss[il+1], hw));
    }
    __syncthreads();

    bool msk = (dist <= sq[0]);
    #pragma unroll
    for (int bnd = 0; bnd < 9; bnd++)
        msk = msk || (dist >= sq[1 + 2*bnd] && dist <= sq[2 + 2*bnd]);
    msk = msk || (xmean <= CONGEST_F32);

    mask[((size_t)b*NP + n)*NP + t] = msk ? (unsigned char)1 : (unsigned char)0;
}

// ---------------------------------------------------------------------------
// SGEMM (R8 shape): C = A @ W^T + bias, 64x64x16 tiles, 4x4 per thread.
// blockIdx.z selects the (A,W,bias,C) tuple (q/k/v fusion). fp32 exact.
// ---------------------------------------------------------------------------
__global__ __launch_bounds__(256) void gemm3_kernel(
    const float* __restrict__ A0, const float* __restrict__ A1, const float* __restrict__ A2,
    const float* __restrict__ W0, const float* __restrict__ W1, const float* __restrict__ W2,
    const float* __restrict__ b0, const float* __restrict__ b1, const float* __restrict__ b2,
    float* __restrict__ C0, float* __restrict__ C1, float* __restrict__ C2)
{
    const int sel = blockIdx.z;
    const float* A    = sel == 0 ? A0 : (sel == 1 ? A1 : A2);
    const float* W    = sel == 0 ? W0 : (sel == 1 ? W1 : W2);
    const float* bias = sel == 0 ? b0 : (sel == 1 ? b1 : b2);
    float*       C    = sel == 0 ? C0 : (sel == 1 ? C1 : C2);

    __shared__ float As[64][17];
    __shared__ float Ws[64][17];
    const int bm = blockIdx.x * 64;
    const int bn = blockIdx.y * 64;
    const int tid = threadIdx.x;
    const int tx4 = (tid & 15) * 4, ty4 = (tid >> 4) * 4;

    float acc[4][4] = {};
    for (int k0 = 0; k0 < 128; k0 += 16) {
        #pragma unroll
        for (int l = 0; l < 4; l++) {
            int idx = tid + l*256;
            int row = idx >> 4, kk = idx & 15;
            As[row][kk] = A[(size_t)(bm+row)*128 + k0 + kk];
            Ws[row][kk] = W[(bn+row)*128 + k0 + kk];
        }
        __syncthreads();
        #pragma unroll
        for (int kk = 0; kk < 16; kk++) {
            float a[4], w[4];
            #pragma unroll
            for (int i = 0; i < 4; i++) a[i] = As[ty4+i][kk];
            #pragma unroll
            for (int j = 0; j < 4; j++) w[j] = Ws[tx4+j][kk];
            #pragma unroll
            for (int i = 0; i < 4; i++)
                #pragma unroll
                for (int j = 0; j < 4; j++)
                    acc[i][j] += a[i] * w[j];
        }
        __syncthreads();
    }
    #pragma unroll
    for (int i = 0; i < 4; i++)
        #pragma unroll
        for (int j = 0; j < 4; j++)
            C[(size_t)(bm+ty4+i)*128 + bn+tx4+j] = acc[i][j] + bias[bn+tx4+j];
}

// ---------------------------------------------------------------------------
// Attention (R8 shape): one block per (b,s,h); 2-query register blocking.
// Changes vs R8: __expf (MUFU) instead of expf; float4 Q loads.
// ---------------------------------------------------------------------------
__global__ __launch_bounds__(256) void attn_kernel(const float* __restrict__ gq,
                                                   const float* __restrict__ gk,
                                                   const float* __restrict__ gv,
                                                   const unsigned char* __restrict__ gmask,
                                                   float* __restrict__ gout) {
    extern __shared__ float sh[];          // Kt[16][512] | Vt[16][512]
    float* Kt = sh;
    float* Vt = sh + HDp*NP;

    const int blk = blockIdx.x;
    const int h   = blk & (HH-1);
    const int bs  = blk >> 3;              // b*S + s
    const int b   = bs / SSS;

    const float* kbase = gk + (size_t)bs*NP*DD + h*HDp;
    const float* vbase = gv + (size_t)bs*NP*DD + h*HDp;
    const float* qbase = gq + (size_t)bs*NP*DD + h*HDp;
    float*       obase = gout + (size_t)bs*NP*DD + h*HDp;
    const unsigned char* maskb = gmask + (size_t)b*NP*NP;

    const int tid = threadIdx.x;
    for (int i = tid; i < NP*4; i += 256) {
        int m = i >> 2, d4 = (i & 3) * 4;
        float4 kv = *(const float4*)&kbase[(size_t)m*DD + d4];
        float4 vv = *(const float4*)&vbase[(size_t)m*DD + d4];
        Kt[(d4+0)*NP+m] = kv.x; Kt[(d4+1)*NP+m] = kv.y;
        Kt[(d4+2)*NP+m] = kv.z; Kt[(d4+3)*NP+m] = kv.w;
        Vt[(d4+0)*NP+m] = vv.x; Vt[(d4+1)*NP+m] = vv.y;
        Vt[(d4+2)*NP+m] = vv.z; Vt[(d4+3)*NP+m] = vv.w;
    }
    __syncthreads();

    const int warp = tid >> 5, lane = tid & 31;

    for (int it = 0; it < 32; ++it) {
        const int n0 = warp*64 + it*2;     // queries n0, n0+1

        float q0[16], q1[16];
        #pragma unroll
        for (int d4 = 0; d4 < 16; d4 += 4) {
            float4 t0 = *(const float4*)&qbase[(size_t)n0*DD + d4];
            float4 t1 = *(const float4*)&qbase[(size_t)(n0+1)*DD + d4];
            q0[d4] = t0.x; q0[d4+1] = t0.y; q0[d4+2] = t0.z; q0[d4+3] = t0.w;
            q1[d4] = t1.x; q1[d4+1] = t1.y; q1[d4+2] = t1.z; q1[d4+3] = t1.w;
        }

        const unsigned char* mr0 = maskb + (size_t)n0*NP;
        const unsigned char* mr1 = mr0 + NP;

        float lg0[16], lg1[16];
        #pragma unroll
        for (int i = 0; i < 16; i++) {
            const int m = i*32 + lane;
            float a0 = 0.f, a1 = 0.f;
            #pragma unroll
            for (int d = 0; d < 16; d++) {
                float kv = Kt[d*NP + m];
                a0 += q0[d]*kv;
                a1 += q1[d]*kv;
            }
            lg0[i] = mr0[m] ? a0*0.25f : -INFINITY;
            lg1[i] = mr1[m] ? a1*0.25f : -INFINITY;
        }

        // softmax (warp-wide max/sum); __expf = MUFU EX2 path
        float mx0 = -INFINITY, mx1 = -INFINITY;
        #pragma unroll
        for (int i = 0; i < 16; i++) { mx0 = fmaxf(mx0, lg0[i]); mx1 = fmaxf(mx1, lg1[i]); }
        #pragma unroll
        for (int off = 16; off; off >>= 1) {
            mx0 = fmaxf(mx0, __shfl_xor_sync(0xffffffffu, mx0, off));
            mx1 = fmaxf(mx1, __shfl_xor_sync(0xffffffffu, mx1, off));
        }
        float s0 = 0.f, s1 = 0.f;
        #pragma unroll
        for (int i = 0; i < 16; i++) {
            lg0[i] = __expf(lg0[i] - mx0);  s0 += lg0[i];
            lg1[i] = __expf(lg1[i] - mx1);  s1 += lg1[i];
        }
        #pragma unroll
        for (int off = 16; off; off >>= 1) {
            s0 += __shfl_xor_sync(0xffffffffu, s0, off);
            s1 += __shfl_xor_sync(0xffffffffu, s1, off);
        }

        // PV
        float acc0[16] = {}, acc1[16] = {};
        #pragma unroll
        for (int i = 0; i < 16; i++) {
            const int m = i*32 + lane;
            const float p0 = lg0[i], p1 = lg1[i];
            #pragma unroll
            for (int d = 0; d < 16; d++) {
                float vv = Vt[d*NP + m];
                acc0[d] += p0*vv;
                acc1[d] += p1*vv;
            }
        }
        #pragma unroll
        for (int off = 16; off; off >>= 1)
            #pragma unroll
            for (int d = 0; d < 16; d++) {
                acc0[d] += __shfl_xor_sync(0xffffffffu, acc0[d], off);
                acc1[d] += __shfl_xor_sync(0xffffffffu, acc1[d], off);
            }

        const float inv0 = 1.0f / s0, inv1 = 1.0f / s1;
        float w0 = 0.f, w1 = 0.f;
        #pragma unroll
        for (int d = 0; d < 16; d++)
            if (lane == d) { w0 = acc0[d]; w1 = acc1[d]; }
        if (lane < 16) {
            obase[(size_t)n0*DD + lane]     = w0 * inv0;
            obase[(size_t)(n0+1)*DD + lane] = w1 * inv1;
        }
    }
}

// ---------------------------------------------------------------------------
extern "C" void kernel_launch(void* const* d_in, const int* in_sizes, int n_in,
                              void* d_out, int out_size) {
    const float* query = (const float*)d_in[0];
    const float* key   = (const float*)d_in[1];
    const float* value = (const float*)d_in[2];
    const float* x     = (const float*)d_in[3];
    const float* Wq    = (const float*)d_in[4];
    const float* bq    = (const float*)d_in[5];
    const float* Wk    = (const float*)d_in[6];
    const float* bk    = (const float*)d_in[7];
    const float* Wv    = (const float*)d_in[8];
    const float* bv    = (const float*)d_in[9];
    const float* Wo    = (const float*)d_in[10];
    const float* bo    = (const float*)d_in[11];
    float* out = (float*)d_out;

    float *pq, *pk, *pv, *pao; unsigned char* pmask;
    cudaGetSymbolAddress((void**)&pq,    g_q);
    cudaGetSymbolAddress((void**)&pk,    g_k);
    cudaGetSymbolAddress((void**)&pv,    g_v);
    cudaGetSymbolAddress((void**)&pao,   g_ao);
    cudaGetSymbolAddress((void**)&pmask, g_mask);

    cudaFuncSetAttribute(attn_kernel, cudaFuncAttributeMaxDynamicSharedMemorySize, 65536);

    // 1) LSH mask (frozen numerics)
    mask_kernel<<<dim3(NP, BB), 512>>>(x, pmask);

    // 2) q/k/v projections fused into one launch (z selects tuple)
    gemm3_kernel<<<dim3(MTOT/64, 2, 3), 256>>>(query, key, value,
                                               Wq, Wk, Wv,
                                               bq, bk, bv,
                                               pq, pk, pv);

    // 3) attention
    attn_kernel<<<BB*SSS*HH, 256, 65536>>>(pq, pk, pv, pmask, pao);

    // 4) output projection
    gemm3_kernel<<<dim3(MTOT/64, 2, 1), 256>>>(pao, pao, pao,
                                               Wo, Wo, Wo,
                                               bo, bo, bo,
                                               out, out, out);
}